// round 14
// baseline (speedup 1.0000x reference)
#include <cuda_runtime.h>
#include <cuda_bf16.h>

#define B_   128
#define T_   1024
#define F_   64
#define H_   256
#define KTOT 320           // F + H
#define NCTA 128
#define NTHR 256

typedef unsigned long long u64;

// ---------------- packed f32x2 helpers (sm_103a FFMA2 path) ----------------
__device__ __forceinline__ u64 pack2(float x, float y) {
    u64 r; asm("mov.b64 %0, {%1,%2};" : "=l"(r) : "f"(x), "f"(y)); return r;
}
__device__ __forceinline__ void fma2(u64& d, u64 a, u64 b) {
    asm("fma.rn.f32x2 %0, %1, %2, %0;" : "+l"(d) : "l"(a), "l"(b));
}
__device__ __forceinline__ void unpack2(float& x, float& y, u64 v) {
    asm("mov.b64 {%0,%1}, %2;" : "=f"(x), "=f"(y) : "l"(v));
}

// ---------------- static device scratch (no runtime allocs) ----------------
__device__ float d_xT[T_ * F_ * B_];        // [t][f][b]       33.5 MB
__device__ float d_hist[T_ * H_ * B_];      // [s][j][b]      134.2 MB (decoder carry h)
__device__ float d_H[2 * H_ * B_];          // double-buffered h, [buf][j][b]
__device__ unsigned d_bar4[128];            // 4 group-barrier counters, stride 128B

// ---------------- kernel 0: reset barriers + zero h0 ----------------
__global__ void init_kernel() {
    int i = blockIdx.x * blockDim.x + threadIdx.x;   // 32768 = H_*B_
    d_H[i] = 0.0f;                                   // buffer 0 = initial h = 0
    if (i < 128) d_bar4[i] = 0u;
}

// ---------------- nop: pads launch sequence so ncu samples lstm_persistent ----------------
__global__ void nop_kernel() {}

// ---------------- kernel 1: transpose x to [t][f][b] ----------------
__global__ __launch_bounds__(NTHR) void transpose_kernel(const float* __restrict__ ts) {
    __shared__ float tile[F_][B_ + 1];
    int t = blockIdx.x;
    for (int idx = threadIdx.x; idx < B_ * F_; idx += NTHR) {
        int b = idx >> 6, f = idx & 63;
        tile[f][b] = ts[(size_t)b * (T_ * F_) + t * F_ + f];     // coalesced over f
    }
    __syncthreads();
    for (int idx = threadIdx.x; idx < F_ * B_; idx += NTHR) {
        int f = idx >> 7, b = idx & 127;
        d_xT[(size_t)t * (F_ * B_) + f * B_ + b] = tile[f][b];   // coalesced over b
    }
}

// ---------------- kernel 2: persistent LSTM (encoder + decoder) ----------------
// smem floats: Ah[256][32]=8192 | xbuf[2][64][32]=4096 | W[2][320][32]=20480 | stg[2][32][33]=2112
#define SM_AH_OFF  0
#define SM_XB_OFF  8192
#define SM_W_OFF   12288
#define SM_S_OFF   32768
#define SMEM_PERSIST_FLOATS (32768 + 2112)
#define SMEM_PERSIST_BYTES  (SMEM_PERSIST_FLOATS * 4)

__device__ __forceinline__ float sigf(float x) { return 1.0f / (1.0f + __expf(-x)); }

__global__ void __launch_bounds__(NTHR, 1) lstm_persistent(
    const float* __restrict__ Wih_e, const float* __restrict__ Whh_e, const float* __restrict__ b_e,
    const float* __restrict__ Wih_d, const float* __restrict__ Whh_d, const float* __restrict__ b_d)
{
    extern __shared__ float sm[];
    float* Ah   = sm + SM_AH_OFF;           // h operand [j=0..255][32 b]
    float* Xb   = sm + SM_XB_OFF;           // x operand double buffer [2][64][32]
    float* W    = sm + SM_W_OFF;
    float* stg0 = sm + SM_S_OFF;
    float* stg1 = stg0 + 32 * 33;

    const int tid = threadIdx.x;
    const int cta = blockIdx.x;
    const int ms  = cta >> 5;          // 0..3  : 32-batch slice (independent barrier group)
    const int ns  = cta & 31;          // 0..31 : 8-hidden-unit slice
    const int m0  = ms * 32;
    unsigned* barp = &d_bar4[ms * 32];

    // Split-K GEMM coords: 16x8 thread grid per group, 2x4 register tile
    const int gid  = tid >> 7;         // 0/1 : K-group
    const int half = tid & 127;
    const int tx   = half & 7;         // n-quad:  n0 = 4*tx
    const int ty   = half >> 3;        // m-pair:  mm = 2*ty
    const int xk0  = gid * 32;         // x-part: 32 k each (of 64)
    const int hk0  = gid * 128;        // h-part: 128 k each (of 256)
    float* stgW = gid ? stg1 : stg0;

    // update/IO coords
    const int jl = tid >> 5;           // 0..7  local hidden unit
    const int mu = tid & 31;           // 0..31 local batch row
    const int jg = ns * 8 + jl;        // global hidden unit

    // ---- load both phases' weight slices into smem (once) ----
    // W[p][k][n]; column n -> gate g = n>>3, hidden j = ns*8+(n&7); weight row = g*H + j
    for (int idx = tid; idx < 2 * KTOT * 32; idx += NTHR) {
        int p = idx / (KTOT * 32);
        int r = idx - p * (KTOT * 32);
        int k = r >> 5, n = r & 31;
        int row = (n >> 3) * H_ + (ns * 8 + (n & 7));
        const float* Wih = p ? Wih_d : Wih_e;
        const float* Whh = p ? Whh_d : Whh_e;
        W[idx] = (k < F_) ? Wih[row * F_ + k] : Whh[row * H_ + (k - F_)];
    }

    // biases
    const float bie = b_e[0 * H_ + jg], bfe = b_e[1 * H_ + jg],
                bge = b_e[2 * H_ + jg], boe = b_e[3 * H_ + jg];
    const float bid = b_d[0 * H_ + jg], bfd = b_d[1 * H_ + jg],
                bgd = b_d[2 * H_ + jg], bod = b_d[3 * H_ + jg];

    float4* Xv = (float4*)Xb;

    // thread's fixed (r,q) coords for 2-float4-per-thread x staging
    const int xr0r = tid >> 3,          xr0q = tid & 7;          // i = tid
    const int xr1r = (tid + NTHR) >> 3, xr1q = (tid + NTHR) & 7; // i = tid+256

    // ---- prologue: stage x(0) into xbuf[0]; carry regs = x(1) ----
    float4 xc0, xc1;
    {
        const float4* xs0 = (const float4*)(d_xT + m0);                      // t=0
        Xv[xr0r * 8 + xr0q] = __ldg(xs0 + xr0r * (B_ / 4) + xr0q);
        Xv[xr1r * 8 + xr1q] = __ldg(xs0 + xr1r * (B_ / 4) + xr1q);
        const float4* xs1 = (const float4*)(d_xT + (size_t)(F_ * B_) + m0);  // t=1
        xc0 = __ldg(xs1 + xr0r * (B_ / 4) + xr0q);
        xc1 = __ldg(xs1 + xr1r * (B_ / 4) + xr1q);
    }

    float c_reg = 0.0f;
    __syncthreads();   // weights + x0 ready

    for (int step = 0; step < 2 * T_; ++step) {
        const bool dec = (step >= T_);
        const float* Wp = W + (dec ? KTOT * 32 : 0);

        // ---- 1. wait for h(step) ----
        if (tid == 0) {
            const unsigned target = (unsigned)step * 32u;
            unsigned v;
            do {
                asm volatile("ld.acquire.gpu.global.u32 %0, [%1];"
                             : "=r"(v) : "l"(barp) : "memory");
            } while (v < target);
        }
        __syncthreads();

        // ---- 2. store carried x(step+1) into xbuf[(step+1)&1] ----
        if (step + 1 < 2 * T_) {
            float4* dst = Xv + ((step + 1) & 1) * 512;
            dst[xr0r * 8 + xr0q] = xc0;
            dst[xr1r * 8 + xr1q] = xc1;
        }

        // ---- 3. issue h(step) loads (latency hidden by x-part GEMM below) ----
        float4 hreg[8];
        {
            const float4* hsrc = (const float4*)(d_H + (step & 1) * (H_ * B_) + m0);
            #pragma unroll
            for (int u = 0; u < 8; ++u) {
                int i = tid + u * NTHR;
                int r = i >> 3, q = i & 7;
                hreg[u] = __ldcg(hsrc + r * (B_ / 4) + q);
            }
        }

        // ---- 4. x-part GEMM from xbuf[step&1] ----
        u64 c00 = 0ull, c01 = 0ull, c10 = 0ull, c11 = 0ull;
        {
            const float* Xp = Xb + (step & 1) * (64 * 32) + 2 * ty;
            const float* Bp = Wp + 4 * tx;
            #pragma unroll 8
            for (int kk = 0; kk < 32; ++kk) {
                int k = xk0 + kk;
                float2 av = *(const float2*)(Xp + k * 32);
                ulonglong2 bb = *(const ulonglong2*)(Bp + k * 32);
                u64 a0 = pack2(av.x, av.x);
                u64 a1 = pack2(av.y, av.y);
                fma2(c00, a0, bb.x); fma2(c01, a0, bb.y);
                fma2(c10, a1, bb.x); fma2(c11, a1, bb.y);
            }
        }

        // ---- 5. store h into smem Ah ----
        {
            float4* Av = (float4*)Ah;
            #pragma unroll
            for (int u = 0; u < 8; ++u) {
                int i = tid + u * NTHR;
                int r = i >> 3, q = i & 7;
                Av[r * 8 + q] = hreg[u];
            }
        }
        __syncthreads();

        // ---- 6. h-part GEMM (128 k per group) ----
        {
            const float* Ap = Ah + 2 * ty;
            const float* Bp = Wp + (F_ * 32) + 4 * tx;     // h rows start at k=64
            #pragma unroll 8
            for (int kk = 0; kk < 128; ++kk) {
                int k = hk0 + kk;
                float2 av = *(const float2*)(Ap + k * 32);
                ulonglong2 bb = *(const ulonglong2*)(Bp + k * 32);
                u64 a0 = pack2(av.x, av.x);
                u64 a1 = pack2(av.y, av.y);
                fma2(c00, a0, bb.x); fma2(c01, a0, bb.y);
                fma2(c10, a1, bb.x); fma2(c11, a1, bb.y);
            }
        }

        // ---- 7. write gate partials ----
        {
            float v0, v1, v2, v3;
            float* r0 = stgW + (2 * ty)     * 33 + 4 * tx;
            float* r1 = stgW + (2 * ty + 1) * 33 + 4 * tx;
            unpack2(v0, v1, c00); unpack2(v2, v3, c01);
            r0[0] = v0; r0[1] = v1; r0[2] = v2; r0[3] = v3;
            unpack2(v0, v1, c10); unpack2(v2, v3, c11);
            r1[0] = v0; r1[1] = v1; r1[2] = v2; r1[3] = v3;
        }
        __syncthreads();

        // ---- 8. activations + cell update for (mu, jl) ----
        float gi = stg0[mu * 33 +      jl] + stg1[mu * 33 +      jl] + (dec ? bid : bie);
        float gf = stg0[mu * 33 +  8 + jl] + stg1[mu * 33 +  8 + jl] + (dec ? bfd : bfe);
        float gg = stg0[mu * 33 + 16 + jl] + stg1[mu * 33 + 16 + jl] + (dec ? bgd : bge);
        float go = stg0[mu * 33 + 24 + jl] + stg1[mu * 33 + 24 + jl] + (dec ? bod : boe);
        gi = sigf(gi); gf = sigf(gf); go = sigf(go);
        gg = tanhf(gg);
        c_reg = gf * c_reg + gi * gg;
        float h = go * tanhf(c_reg);

        __stcg(d_H + ((step + 1) & 1) * (H_ * B_) + jg * B_ + m0 + mu, h);

        // ---- 9. arrive (release) ----
        __syncthreads();
        if (tid == 0) {
            asm volatile("red.release.gpu.global.add.u32 [%0], 1;"
                         :: "l"(barp) : "memory");
        }

        // ======== post-arrive: off the group's critical path ========

        // ---- 10. decoder-carry history ----
        if (step >= T_ - 1 && step < 2 * T_ - 1) {
            int s = step - (T_ - 1);
            d_hist[(size_t)s * (H_ * B_) + jg * B_ + m0 + mu] = h;
        }

        // ---- 11. issue x(step+2) loads into carry regs (STS next iteration) ----
        if (step + 2 < 2 * T_) {
            const int sn = step + 2;
            const int tn = (sn >= T_) ? (2 * T_ - 1 - sn) : sn;
            const float4* xs2 = (const float4*)(d_xT + (size_t)tn * (F_ * B_) + m0);
            xc0 = __ldg(xs2 + xr0r * (B_ / 4) + xr0q);
            xc1 = __ldg(xs2 + xr1r * (B_ / 4) + xr1q);
        }
    }
}

// ---------------- kernel 3: output projection (f32x2) ----------------
// out[b][t][f] = sum_j hist[T-1-t][j][b] * W_out[f][j] + b_out[f]
#define SMEM_PROJ_BYTES ((H_ * F_ + F_) * 4)

__global__ void __launch_bounds__(256) proj_kernel(
    const float* __restrict__ Wout, const float* __restrict__ bout, float* __restrict__ out)
{
    extern __shared__ float sm[];
    float* Ws = sm;              // [j][f] transposed W_out
    float* bs = sm + H_ * F_;

    const int t = blockIdx.x;
    const int s = T_ - 1 - t;
    for (int i = threadIdx.x; i < H_ * F_; i += 256) {
        int j = i >> 6, f = i & 63;
        Ws[i] = Wout[f * H_ + j];
    }
    if (threadIdx.x < F_) bs[threadIdx.x] = bout[threadIdx.x];
    __syncthreads();

    const int b  = threadIdx.x & 127;
    const int fg = (threadIdx.x >> 7) * 32;     // f-group: 0 or 32

    u64 acc[16];                                // pairs (fg+2i, fg+2i+1)
    #pragma unroll
    for (int i = 0; i < 16; ++i) acc[i] = pack2(bs[fg + 2 * i], bs[fg + 2 * i + 1]);

    const float* hrow = d_hist + (size_t)s * (H_ * B_) + b;
    #pragma unroll 8
    for (int j = 0; j < H_; ++j) {
        float hv = __ldcs(hrow + (size_t)j * B_);    // streaming: hist read once
        u64 hh = pack2(hv, hv);
        const ulonglong2* wr = (const ulonglong2*)(Ws + j * F_ + fg);
        #pragma unroll
        for (int i = 0; i < 8; ++i) {
            ulonglong2 wv = wr[i];
            fma2(acc[2 * i],     hh, wv.x);
            fma2(acc[2 * i + 1], hh, wv.y);
        }
    }

    float* orow = out + (size_t)b * (T_ * F_) + t * F_ + fg;
    #pragma unroll
    for (int i = 0; i < 16; ++i) {
        float lo, hi; unpack2(lo, hi, acc[i]);
        *(float2*)(orow + 2 * i) = make_float2(lo, hi);
    }
}

// ---------------- launch ----------------
extern "C" void kernel_launch(void* const* d_in, const int* in_sizes, int n_in,
                              void* d_out, int out_size) {
    const float* ts    = (const float*)d_in[0];
    const float* Wih_e = (const float*)d_in[1];
    const float* Whh_e = (const float*)d_in[2];
    const float* b_e   = (const float*)d_in[3];
    const float* Wih_d = (const float*)d_in[4];
    const float* Whh_d = (const float*)d_in[5];
    const float* b_d   = (const float*)d_in[6];
    const float* Wout  = (const float*)d_in[7];
    const float* bout  = (const float*)d_in[8];
    float* out = (float*)d_out;

    cudaFuncSetAttribute(lstm_persistent, cudaFuncAttributeMaxDynamicSharedMemorySize,
                         SMEM_PERSIST_BYTES);
    cudaFuncSetAttribute(proj_kernel, cudaFuncAttributeMaxDynamicSharedMemorySize,
                         SMEM_PROJ_BYTES);

    init_kernel<<<128, 256>>>();          // my-launch 0
    transpose_kernel<<<T_, NTHR>>>(ts);   // my-launch 1
    nop_kernel<<<1, 32>>>();              // my-launch 2  (pad: profiled slot = my-launch 3)
    lstm_persistent<<<NCTA, NTHR, SMEM_PERSIST_BYTES>>>(Wih_e, Whh_e, b_e,   // my-launch 3
                                                        Wih_d, Whh_d, b_d);
    proj_kernel<<<T_, 256, SMEM_PROJ_BYTES>>>(Wout, bout, out);              // my-launch 4
}